// round 7
// baseline (speedup 1.0000x reference)
#include <cuda_runtime.h>
#include <cuda_bf16.h>
#include <cuda_fp16.h>
#include <mma.h>

using namespace nvcuda;

#define NUSER 50000
#define NITEM 100000
#define NNODE 150000
#define NPAD  150016          // multiple of 512 (293*512)
#define NB_SCAN 293
#define NNZ   2000000
#define D     80              // 64 light + 16 mm, fused (augmented)
#define BATCH 1024

// ---------------- static device scratch (no cudaMalloc allowed) ----------------
// fp16 propagation buffers: light (64 dims, 128B rows) and mm (16 dims, 32B rows)
__device__ __align__(256) __half g_L[4][(size_t)NPAD * 64];
__device__ __align__(256) __half g_M[4][(size_t)NPAD * 16];

__device__ int   g_cnt[NPAD];
__device__ int   g_rowptr[NPAD];
__device__ int   g_cursor[NPAD];
__device__ int   g_bsum[512];
__device__ int   g_boff[512];
__device__ int   g_ci[NNZ];
__device__ float g_cv[NNZ];
__device__ __align__(256) __nv_bfloat16 g_UA[BATCH * D];            // augmented users
__device__ __align__(256) __nv_bfloat16 g_IA[(size_t)NITEM * D];    // augmented items

__device__ __forceinline__ float sigmoidf(float x) {
    return 1.0f / (1.0f + __expf(-x));
}

// ---------------- CSR construction ----------------
__global__ void k_zero_cnt() {
    int i = blockIdx.x * blockDim.x + threadIdx.x;
    if (i < NPAD) g_cnt[i] = 0;
}

__global__ void k_count(const int* __restrict__ rows) {
    int i = blockIdx.x * blockDim.x + threadIdx.x;
    if (i < NNZ) atomicAdd(&g_cnt[rows[i]], 1);
}

__global__ void k_scan_block() {
    __shared__ int s[512];
    int t = threadIdx.x;
    int i = blockIdx.x * 512 + t;
    int v = g_cnt[i];
    s[t] = v;
    __syncthreads();
    #pragma unroll
    for (int off = 1; off < 512; off <<= 1) {
        int x = (t >= off) ? s[t - off] : 0;
        __syncthreads();
        s[t] += x;
        __syncthreads();
    }
    g_rowptr[i] = s[t] - v;           // block-local exclusive
    if (t == 511) g_bsum[blockIdx.x] = s[511];
}

__global__ void k_scan_bsum() {
    __shared__ int s[512];
    int t = threadIdx.x;
    int v = (t < NB_SCAN) ? g_bsum[t] : 0;
    s[t] = v;
    __syncthreads();
    #pragma unroll
    for (int off = 1; off < 512; off <<= 1) {
        int x = (t >= off) ? s[t - off] : 0;
        __syncthreads();
        s[t] += x;
        __syncthreads();
    }
    g_boff[t] = s[t] - v;             // exclusive
}

__global__ void k_scan_add() {
    int t = threadIdx.x;
    int i = blockIdx.x * 512 + t;
    int r = g_rowptr[i] + g_boff[blockIdx.x];
    g_rowptr[i] = r;
    g_cursor[i] = r;
}

__global__ void k_fill(const int* __restrict__ rows, const int* __restrict__ cols,
                       const float* __restrict__ vals) {
    int i = blockIdx.x * blockDim.x + threadIdx.x;
    if (i >= NNZ) return;
    int r = rows[i];
    int p = atomicAdd(&g_cursor[r], 1);
    g_ci[p] = cols[i];
    g_cv[p] = vals[i];
}

// ---------------- init layer-0 fp16 buffers ----------------
// one thread per half2 pair: 32 light pairs + 8 mm pairs per node
__global__ void k_init(const float* __restrict__ eu, const float* __restrict__ ei,
                       const float* __restrict__ mu, const float* __restrict__ mi) {
    int i = blockIdx.x * blockDim.x + threadIdx.x;
    if (i >= NNODE * 40) return;
    int n = i / 40, j = i % 40;
    float2 f;
    if (j < 32) {
        const float* src = (n < NUSER) ? (eu + (size_t)n * 64)
                                       : (ei + (size_t)(n - NUSER) * 64);
        f = *(const float2*)(src + 2 * j);
        ((__half2*)g_L[0])[(size_t)n * 32 + j] = __float22half2_rn(f);
    } else {
        int jm = j - 32;
        const float* src = (n < NUSER) ? (mu + (size_t)n * 16)
                                       : (mi + (size_t)(n - NUSER) * 16);
        f = *(const float2*)(src + 2 * jm);
        ((__half2*)g_M[0])[(size_t)n * 8 + jm] = __float22half2_rn(f);
    }
}

// ---------------- fused gather SpMM (light 64 + mm 16), one row per warp ----------------
__global__ void k_spmm(int layer) {
    const __half2* __restrict__ Lin  = (const __half2*)g_L[layer];
    __half2* __restrict__       Lout = (__half2*)g_L[layer + 1];
    const __half2* __restrict__ Min  = (const __half2*)g_M[layer];
    __half2* __restrict__       Mout = (__half2*)g_M[layer + 1];

    int row = blockIdx.x * (blockDim.x >> 5) + (threadIdx.x >> 5);
    int lane = threadIdx.x & 31;
    int start = g_rowptr[row];
    int deg = g_cnt[row];
    const int*   ci = g_ci + start;
    const float* cv = g_cv + start;

    float aLx = 0.f, aLy = 0.f, aMx = 0.f, aMy = 0.f;
    #pragma unroll 4
    for (int e = 0; e < deg; e++) {
        int c = __ldg(ci + e);
        float v = __ldg(cv + e);
        float2 f = __half22float2(__ldg(Lin + (size_t)c * 32 + lane));
        aLx += v * f.x;
        aLy += v * f.y;
        if (lane < 8) {
            float2 g = __half22float2(__ldg(Min + (size_t)c * 8 + lane));
            aMx += v * g.x;
            aMy += v * g.y;
        }
    }
    Lout[(size_t)row * 32 + lane] = __float22half2_rn(make_float2(aLx, aLy));
    if (lane < 8)
        Mout[(size_t)row * 8 + lane] = __float22half2_rn(make_float2(aMx, aMy));
}

// ---------------- augmented user / item builders (bf16, /4 folded in) ----------------
__device__ __forceinline__ float node_dim_sum(int n, int d) {
    // (sum over 4 layers of light[d] + mm[d>>2]) * 0.25
    float s = 0.f;
    #pragma unroll
    for (int l = 0; l < 4; l++) {
        s += __half2float(g_L[l][(size_t)n * 64 + d]);
        s += __half2float(g_M[l][(size_t)n * 16 + (d >> 2)]);
    }
    return 0.25f * s;
}

__global__ void k_uaug(const int* __restrict__ users, const float* __restrict__ bias_user) {
    int i = blockIdx.x * blockDim.x + threadIdx.x;
    if (i >= BATCH * D) return;
    int b = i / D, d = i % D;
    int u = users[b];
    float v;
    if (d < 64)      v = node_dim_sum(u, d);
    else if (d == 64) v = bias_user[u];
    else if (d == 65) v = 1.0f;
    else              v = 0.0f;
    g_UA[i] = __float2bfloat16(v);
}

__global__ void k_iaug(const float* __restrict__ bias_item) {
    int i = blockIdx.x * blockDim.x + threadIdx.x;
    if (i >= NITEM * D) return;
    int it = i / D, d = i % D;
    float v;
    if (d < 64)      v = node_dim_sum(NUSER + it, d);
    else if (d == 64) v = 1.0f;
    else if (d == 65) v = bias_item[it];
    else              v = 0.0f;
    g_IA[i] = __float2bfloat16(v);
}

// ---------------- GEMM: [1024,80]bf16 x [N,80]bf16^T -> sigmoid -> f32 ----------------
// block tile 128x128, 8 warps (32x64 each), K=80. Dynamic smem:
//   phase 1: As[128][88] bf16 + Bs[128][88] bf16  (45056 B)
//   phase 2 (reused): Cs[128][132] f32            (67584 B)  -> stcs float4 stores
#define GEMM_SMEM 67584
__global__ void __launch_bounds__(256) k_gemm(float* __restrict__ out) {
    extern __shared__ char smem[];
    __nv_bfloat16* As = (__nv_bfloat16*)smem;            // 128 x 88
    __nv_bfloat16* Bs = As + 128 * 88;                   // 128 x 88
    float* Cs = (float*)smem;                            // 128 x 132 (reuse)

    int m0 = blockIdx.y * 128;
    int n0 = blockIdx.x * 128;
    int t = threadIdx.x;

    const uint4* ua = (const uint4*)g_UA;   // 10 uint4 per 80-bf16 row
    const uint4* ia = (const uint4*)g_IA;
    const uint4 zero4 = make_uint4(0, 0, 0, 0);
    #pragma unroll
    for (int idx = t; idx < 1280; idx += 256) {
        int r = idx / 10, c = idx % 10;
        *(uint4*)(As + r * 88 + c * 8) = ua[(size_t)(m0 + r) * 10 + c];
    }
    #pragma unroll
    for (int idx = t; idx < 1280; idx += 256) {
        int r = idx / 10, c = idx % 10;
        int gr = n0 + r;
        *(uint4*)(Bs + r * 88 + c * 8) = (gr < NITEM) ? ia[(size_t)gr * 10 + c] : zero4;
    }
    __syncthreads();

    int w = t >> 5;
    int wm = (w >> 1) * 32;   // 0,32,64,96
    int wn = (w & 1) * 64;    // 0,64

    wmma::fragment<wmma::accumulator, 16, 16, 16, float> acc[2][4];
    #pragma unroll
    for (int i = 0; i < 2; i++)
        #pragma unroll
        for (int j = 0; j < 4; j++)
            wmma::fill_fragment(acc[i][j], 0.0f);

    #pragma unroll
    for (int k = 0; k < 80; k += 16) {
        wmma::fragment<wmma::matrix_a, 16, 16, 16, __nv_bfloat16, wmma::row_major> a[2];
        wmma::fragment<wmma::matrix_b, 16, 16, 16, __nv_bfloat16, wmma::col_major> b[4];
        #pragma unroll
        for (int i = 0; i < 2; i++)
            wmma::load_matrix_sync(a[i], As + (wm + 16 * i) * 88 + k, 88);
        #pragma unroll
        for (int j = 0; j < 4; j++)
            wmma::load_matrix_sync(b[j], Bs + (wn + 16 * j) * 88 + k, 88);
        #pragma unroll
        for (int i = 0; i < 2; i++)
            #pragma unroll
            for (int j = 0; j < 4; j++)
                wmma::mma_sync(acc[i][j], a[i], b[j], acc[i][j]);
    }

    // stage into shared (reusing As/Bs memory), then streamed float4 stores
    __syncthreads();
    #pragma unroll
    for (int i = 0; i < 2; i++)
        #pragma unroll
        for (int j = 0; j < 4; j++)
            wmma::store_matrix_sync(Cs + (wm + 16 * i) * 132 + wn + 16 * j,
                                    acc[i][j], 132, wmma::mem_row_major);
    __syncthreads();

    #pragma unroll
    for (int idx = t; idx < 128 * 32; idx += 256) {
        int r = idx >> 5, c4 = idx & 31;
        int gcol = n0 + c4 * 4;
        if (gcol >= NITEM) continue;
        float4 v = *(float4*)(Cs + r * 132 + c4 * 4);
        v.x = sigmoidf(v.x); v.y = sigmoidf(v.y);
        v.z = sigmoidf(v.z); v.w = sigmoidf(v.w);
        __stcs((float4*)(out + (size_t)(m0 + r) * NITEM + gcol), v);
    }
}

// ---------------- launcher ----------------
extern "C" void kernel_launch(void* const* d_in, const int* in_sizes, int n_in,
                              void* d_out, int out_size) {
    const float* emb_user  = (const float*)d_in[0];
    const float* emb_item  = (const float*)d_in[1];
    const float* bias_user = (const float*)d_in[2];
    const float* bias_item = (const float*)d_in[3];
    const float* mm_user   = (const float*)d_in[4];
    const float* mm_item   = (const float*)d_in[5];
    const float* vals      = (const float*)d_in[6];
    const int*   users     = (const int*)d_in[7];
    const int*   rows      = (const int*)d_in[8];
    const int*   cols      = (const int*)d_in[9];
    float* out = (float*)d_out;

    cudaFuncSetAttribute(k_gemm, cudaFuncAttributeMaxDynamicSharedMemorySize, GEMM_SMEM);

    // CSR build
    k_zero_cnt<<<(NPAD + 255) / 256, 256>>>();
    k_count<<<(NNZ + 255) / 256, 256>>>(rows);
    k_scan_block<<<NB_SCAN, 512>>>();
    k_scan_bsum<<<1, 512>>>();
    k_scan_add<<<NB_SCAN, 512>>>();
    k_fill<<<(NNZ + 255) / 256, 256>>>(rows, cols, vals);

    // layer-0 fp16 buffers
    k_init<<<(NNODE * 40 + 255) / 256, 256>>>(emb_user, emb_item, mm_user, mm_item);

    // 3 propagation layers (fused light+mm gather, fp16 storage, fp32 accum)
    for (int L = 0; L < 3; L++)
        k_spmm<<<NPAD / 8, 256>>>(L);

    // augmented embeddings
    k_uaug<<<(BATCH * D + 255) / 256, 256>>>(users, bias_user);
    k_iaug<<<(NITEM * D + 255) / 256, 256>>>(bias_item);

    // GEMM (tail folded in via predication)
    dim3 grid((NITEM + 127) / 128, BATCH / 128);
    k_gemm<<<grid, 256, GEMM_SMEM>>>(out);
}

// round 8
// speedup vs baseline: 1.0620x; 1.0620x over previous
#include <cuda_runtime.h>
#include <cuda_bf16.h>
#include <cuda_fp16.h>
#include <mma.h>

using namespace nvcuda;

#define NUSER 50000
#define NITEM 100000
#define NNODE 150000
#define NPAD  150016          // multiple of 512 (293*512)
#define NB_SCAN 293
#define NNZ   2000000
#define D     80              // 64 light + 16 mm, fused (augmented)
#define BATCH 1024
#define NTAIL0 99968          // 781*128

// ---------------- static device scratch (no cudaMalloc allowed) ----------------
// fp16 propagation buffers: light (64 dims, 128B rows) and mm (16 dims, 32B rows)
__device__ __align__(256) __half g_L[4][(size_t)NPAD * 64];
__device__ __align__(256) __half g_M[4][(size_t)NPAD * 16];

__device__ int   g_cnt[NPAD];
__device__ int   g_rowptr[NPAD];
__device__ int   g_cursor[NPAD];
__device__ int   g_bsum[512];
__device__ int   g_boff[512];
__device__ __align__(256) int2 g_edge[NNZ];          // (col, bitcast(val))
__device__ __align__(256) __nv_bfloat16 g_UA[BATCH * D];            // augmented users
__device__ __align__(256) __nv_bfloat16 g_IA[(size_t)NITEM * D];    // augmented items

__device__ __forceinline__ float sigmoidf(float x) {
    return 1.0f / (1.0f + __expf(-x));
}

// ---------------- CSR construction ----------------
__global__ void k_zero_cnt() {
    int i = blockIdx.x * blockDim.x + threadIdx.x;
    if (i < NPAD) g_cnt[i] = 0;
}

__global__ void k_count(const int* __restrict__ rows) {
    int i = blockIdx.x * blockDim.x + threadIdx.x;
    if (i < NNZ) atomicAdd(&g_cnt[rows[i]], 1);
}

__global__ void k_scan_block() {
    __shared__ int s[512];
    int t = threadIdx.x;
    int i = blockIdx.x * 512 + t;
    int v = g_cnt[i];
    s[t] = v;
    __syncthreads();
    #pragma unroll
    for (int off = 1; off < 512; off <<= 1) {
        int x = (t >= off) ? s[t - off] : 0;
        __syncthreads();
        s[t] += x;
        __syncthreads();
    }
    g_rowptr[i] = s[t] - v;           // block-local exclusive
    if (t == 511) g_bsum[blockIdx.x] = s[511];
}

__global__ void k_scan_bsum() {
    __shared__ int s[512];
    int t = threadIdx.x;
    int v = (t < NB_SCAN) ? g_bsum[t] : 0;
    s[t] = v;
    __syncthreads();
    #pragma unroll
    for (int off = 1; off < 512; off <<= 1) {
        int x = (t >= off) ? s[t - off] : 0;
        __syncthreads();
        s[t] += x;
        __syncthreads();
    }
    g_boff[t] = s[t] - v;             // exclusive
}

__global__ void k_scan_add() {
    int t = threadIdx.x;
    int i = blockIdx.x * 512 + t;
    int r = g_rowptr[i] + g_boff[blockIdx.x];
    g_rowptr[i] = r;
    g_cursor[i] = r;
}

__global__ void k_fill(const int* __restrict__ rows, const int* __restrict__ cols,
                       const float* __restrict__ vals) {
    int i = blockIdx.x * blockDim.x + threadIdx.x;
    if (i >= NNZ) return;
    int r = rows[i];
    int p = atomicAdd(&g_cursor[r], 1);
    g_edge[p] = make_int2(cols[i], __float_as_int(vals[i]));
}

// ---------------- init layer-0 fp16 buffers ----------------
// one thread per half2 pair: 32 light pairs + 8 mm pairs per node
__global__ void k_init(const float* __restrict__ eu, const float* __restrict__ ei,
                       const float* __restrict__ mu, const float* __restrict__ mi) {
    int i = blockIdx.x * blockDim.x + threadIdx.x;
    if (i >= NNODE * 40) return;
    int n = i / 40, j = i % 40;
    float2 f;
    if (j < 32) {
        const float* src = (n < NUSER) ? (eu + (size_t)n * 64)
                                       : (ei + (size_t)(n - NUSER) * 64);
        f = *(const float2*)(src + 2 * j);
        ((__half2*)g_L[0])[(size_t)n * 32 + j] = __float22half2_rn(f);
    } else {
        int jm = j - 32;
        const float* src = (n < NUSER) ? (mu + (size_t)n * 16)
                                       : (mi + (size_t)(n - NUSER) * 16);
        f = *(const float2*)(src + 2 * jm);
        ((__half2*)g_M[0])[(size_t)n * 8 + jm] = __float22half2_rn(f);
    }
}

// ---------------- fused gather SpMM (light 64 + mm 16), one row per warp ----------------
// 4-edge manual unroll: 4 independent gather chains in flight per warp (MLP=4)
__global__ void k_spmm(int layer) {
    const __half2* __restrict__ Lin  = (const __half2*)g_L[layer];
    __half2* __restrict__       Lout = (__half2*)g_L[layer + 1];
    const __half2* __restrict__ Min  = (const __half2*)g_M[layer];
    __half2* __restrict__       Mout = (__half2*)g_M[layer + 1];

    int row = blockIdx.x * (blockDim.x >> 5) + (threadIdx.x >> 5);
    int lane = threadIdx.x & 31;
    int start = g_rowptr[row];
    int deg = g_cnt[row];
    const int2* __restrict__ ev = g_edge + start;

    float L0x = 0.f, L0y = 0.f, L1x = 0.f, L1y = 0.f;
    float L2x = 0.f, L2y = 0.f, L3x = 0.f, L3y = 0.f;
    float M0x = 0.f, M0y = 0.f, M1x = 0.f, M1y = 0.f;

    int e = 0;
    for (; e + 4 <= deg; e += 4) {
        int2 e0 = __ldg(ev + e);
        int2 e1 = __ldg(ev + e + 1);
        int2 e2 = __ldg(ev + e + 2);
        int2 e3 = __ldg(ev + e + 3);
        float v0 = __int_as_float(e0.y), v1 = __int_as_float(e1.y);
        float v2 = __int_as_float(e2.y), v3 = __int_as_float(e3.y);
        // 4 independent light gathers
        __half2 h0 = __ldg(Lin + (size_t)e0.x * 32 + lane);
        __half2 h1 = __ldg(Lin + (size_t)e1.x * 32 + lane);
        __half2 h2 = __ldg(Lin + (size_t)e2.x * 32 + lane);
        __half2 h3 = __ldg(Lin + (size_t)e3.x * 32 + lane);
        float2 f0 = __half22float2(h0), f1 = __half22float2(h1);
        float2 f2 = __half22float2(h2), f3 = __half22float2(h3);
        L0x += v0 * f0.x; L0y += v0 * f0.y;
        L1x += v1 * f1.x; L1y += v1 * f1.y;
        L2x += v2 * f2.x; L2y += v2 * f2.y;
        L3x += v3 * f3.x; L3y += v3 * f3.y;
        if (lane < 8) {
            __half2 m0 = __ldg(Min + (size_t)e0.x * 8 + lane);
            __half2 m1 = __ldg(Min + (size_t)e1.x * 8 + lane);
            __half2 m2 = __ldg(Min + (size_t)e2.x * 8 + lane);
            __half2 m3 = __ldg(Min + (size_t)e3.x * 8 + lane);
            float2 g0 = __half22float2(m0), g1 = __half22float2(m1);
            float2 g2 = __half22float2(m2), g3 = __half22float2(m3);
            M0x += v0 * g0.x; M0y += v0 * g0.y;
            M1x += v1 * g1.x; M1y += v1 * g1.y;
            M0x += v2 * g2.x; M0y += v2 * g2.y;
            M1x += v3 * g3.x; M1y += v3 * g3.y;
        }
    }
    for (; e < deg; e++) {
        int2 e0 = __ldg(ev + e);
        float v0 = __int_as_float(e0.y);
        float2 f0 = __half22float2(__ldg(Lin + (size_t)e0.x * 32 + lane));
        L0x += v0 * f0.x; L0y += v0 * f0.y;
        if (lane < 8) {
            float2 g0 = __half22float2(__ldg(Min + (size_t)e0.x * 8 + lane));
            M0x += v0 * g0.x; M0y += v0 * g0.y;
        }
    }

    float lx = (L0x + L1x) + (L2x + L3x);
    float ly = (L0y + L1y) + (L2y + L3y);
    Lout[(size_t)row * 32 + lane] = __float22half2_rn(make_float2(lx, ly));
    if (lane < 8)
        Mout[(size_t)row * 8 + lane] =
            __float22half2_rn(make_float2(M0x + M1x, M0y + M1y));
}

// ---------------- augmented user / item builders (bf16, /4 folded in) ----------------
__device__ __forceinline__ float node_dim_sum(int n, int d) {
    float s = 0.f;
    #pragma unroll
    for (int l = 0; l < 4; l++) {
        s += __half2float(g_L[l][(size_t)n * 64 + d]);
        s += __half2float(g_M[l][(size_t)n * 16 + (d >> 2)]);
    }
    return 0.25f * s;
}

__global__ void k_uaug(const int* __restrict__ users, const float* __restrict__ bias_user) {
    int i = blockIdx.x * blockDim.x + threadIdx.x;
    if (i >= BATCH * D) return;
    int b = i / D, d = i % D;
    int u = users[b];
    float v;
    if (d < 64)       v = node_dim_sum(u, d);
    else if (d == 64) v = bias_user[u];
    else if (d == 65) v = 1.0f;
    else              v = 0.0f;
    g_UA[i] = __float2bfloat16(v);
}

__global__ void k_iaug(const float* __restrict__ bias_item) {
    int i = blockIdx.x * blockDim.x + threadIdx.x;
    if (i >= NITEM * D) return;
    int it = i / D, d = i % D;
    float v;
    if (d < 64)       v = node_dim_sum(NUSER + it, d);
    else if (d == 64) v = 1.0f;
    else if (d == 65) v = bias_item[it];
    else              v = 0.0f;
    g_IA[i] = __float2bfloat16(v);
}

// ---------------- GEMM: [1024,80]bf16 x [N,80]bf16^T -> sigmoid -> f32 ----------------
// block tile 128x128, 8 warps each 32x64, K=80 (5 steps of 16)  [R5-proven form]
__global__ void __launch_bounds__(256) k_gemm(float* __restrict__ out) {
    __shared__ alignas(16) __nv_bfloat16 As[128][88];
    __shared__ alignas(16) __nv_bfloat16 Bs[128][88];
    int m0 = blockIdx.y * 128;
    int n0 = blockIdx.x * 128;
    int t = threadIdx.x;

    const uint4* ua = (const uint4*)g_UA;   // 10 uint4 per row (80 bf16 = 160B)
    const uint4* ia = (const uint4*)g_IA;
    #pragma unroll
    for (int idx = t; idx < 1280; idx += 256) {
        int r = idx / 10, c = idx % 10;
        *(uint4*)(&As[r][c * 8]) = ua[(size_t)(m0 + r) * 10 + c];
    }
    #pragma unroll
    for (int idx = t; idx < 1280; idx += 256) {
        int r = idx / 10, c = idx % 10;
        *(uint4*)(&Bs[r][c * 8]) = ia[(size_t)(n0 + r) * 10 + c];
    }
    __syncthreads();

    int w = t >> 5;
    int wm = (w >> 1) * 32;   // 0,32,64,96
    int wn = (w & 1) * 64;    // 0,64

    wmma::fragment<wmma::accumulator, 16, 16, 16, float> acc[2][4];
    #pragma unroll
    for (int i = 0; i < 2; i++)
        #pragma unroll
        for (int j = 0; j < 4; j++)
            wmma::fill_fragment(acc[i][j], 0.0f);

    #pragma unroll
    for (int k = 0; k < 80; k += 16) {
        wmma::fragment<wmma::matrix_a, 16, 16, 16, __nv_bfloat16, wmma::row_major> a[2];
        wmma::fragment<wmma::matrix_b, 16, 16, 16, __nv_bfloat16, wmma::col_major> b[4];
        #pragma unroll
        for (int i = 0; i < 2; i++)
            wmma::load_matrix_sync(a[i], &As[wm + 16 * i][0] + k, 88);
        #pragma unroll
        for (int j = 0; j < 4; j++)
            wmma::load_matrix_sync(b[j], &Bs[wn + 16 * j][0] + k, 88);
        #pragma unroll
        for (int i = 0; i < 2; i++)
            #pragma unroll
            for (int j = 0; j < 4; j++)
                wmma::mma_sync(acc[i][j], a[i], b[j], acc[i][j]);
    }

    #pragma unroll
    for (int i = 0; i < 2; i++) {
        #pragma unroll
        for (int j = 0; j < 4; j++) {
            #pragma unroll
            for (int e = 0; e < acc[i][j].num_elements; e++)
                acc[i][j].x[e] = sigmoidf(acc[i][j].x[e]);
            wmma::store_matrix_sync(
                out + (size_t)(m0 + wm + 16 * i) * NITEM + (n0 + wn + 16 * j),
                acc[i][j], NITEM, wmma::mem_row_major);
        }
    }
}

// ---------------- tail: columns [99968, 100000) ----------------
__global__ void k_tail(float* __restrict__ out) {
    int i = blockIdx.x * blockDim.x + threadIdx.x;
    if (i >= BATCH * 32) return;
    int b = i >> 5, j = i & 31;
    int n = NTAIL0 + j;
    const __nv_bfloat16* u = g_UA + (size_t)b * D;
    const __nv_bfloat16* v = g_IA + (size_t)n * D;
    float s = 0.f;
    #pragma unroll
    for (int k = 0; k < D; k++)
        s += __bfloat162float(u[k]) * __bfloat162float(v[k]);
    out[(size_t)b * NITEM + n] = sigmoidf(s);
}

// ---------------- launcher ----------------
extern "C" void kernel_launch(void* const* d_in, const int* in_sizes, int n_in,
                              void* d_out, int out_size) {
    const float* emb_user  = (const float*)d_in[0];
    const float* emb_item  = (const float*)d_in[1];
    const float* bias_user = (const float*)d_in[2];
    const float* bias_item = (const float*)d_in[3];
    const float* mm_user   = (const float*)d_in[4];
    const float* mm_item   = (const float*)d_in[5];
    const float* vals      = (const float*)d_in[6];
    const int*   users     = (const int*)d_in[7];
    const int*   rows      = (const int*)d_in[8];
    const int*   cols      = (const int*)d_in[9];
    float* out = (float*)d_out;

    // CSR build
    k_zero_cnt<<<(NPAD + 255) / 256, 256>>>();
    k_count<<<(NNZ + 255) / 256, 256>>>(rows);
    k_scan_block<<<NB_SCAN, 512>>>();
    k_scan_bsum<<<1, 512>>>();
    k_scan_add<<<NB_SCAN, 512>>>();
    k_fill<<<(NNZ + 255) / 256, 256>>>(rows, cols, vals);

    // layer-0 fp16 buffers
    k_init<<<(NNODE * 40 + 255) / 256, 256>>>(emb_user, emb_item, mm_user, mm_item);

    // 3 propagation layers (fused light+mm gather, fp16 storage, fp32 accum, MLP=4)
    for (int L = 0; L < 3; L++)
        k_spmm<<<NPAD / 8, 256>>>(L);

    // augmented embeddings
    k_uaug<<<(BATCH * D + 255) / 256, 256>>>(users, bias_user);
    k_iaug<<<(NITEM * D + 255) / 256, 256>>>(bias_item);

    // main GEMM + tail
    dim3 grid(NTAIL0 / 128, BATCH / 128);
    k_gemm<<<grid, 256>>>(out);
    k_tail<<<(BATCH * 32 + 255) / 256, 256>>>(out);
}